// round 16
// baseline (speedup 1.0000x reference)
#include <cuda_runtime.h>
#include <cuda_fp16.h>
#include <math.h>
#include <stdint.h>
#include <string.h>

// ---------------------------------------------------------------------------
// Problem constants
// ---------------------------------------------------------------------------
#define T_SEQ   2048
#define HIDDEN  2048
#define N_HEADS 16
#define N_KV    4
#define HEAD_DIM 128
#define QKV_N   ((N_HEADS + 2 * N_KV) * HEAD_DIM)   // 3072
#define O_DIM   (N_HEADS * HEAD_DIM)                 // 2048

__device__ uint32_t g_attn_h[T_SEQ * O_DIM / 2];        // fp16 attn out
__device__ uint32_t g_hid_h[T_SEQ * HIDDEN / 2];        // fp16 hidden
__device__ uint32_t g_wqkv_h[(HIDDEN / 2) * QKV_N];     // fp16 w_qkv k-pairs
__device__ uint32_t g_wo_h[(O_DIM / 2) * HIDDEN];       // fp16 w_o   k-pairs
__device__ uint32_t g_q_h[T_SEQ * N_HEADS * 64];        // fp16 Q dim-pairs
__device__ uint32_t g_k_h[N_KV * T_SEQ * 64];           // fp16 K dim-pairs
__device__ uint32_t g_v_h[N_KV * T_SEQ * 64];           // fp16 V dim-pairs

// ---------------------------------------------------------------------------
// helpers
// ---------------------------------------------------------------------------
__device__ __forceinline__ uint32_t packh2(float a, float b) {
    __half2 h = __floats2half2_rn(a, b);
    uint32_t u; memcpy(&u, &h, 4); return u;
}
__device__ __forceinline__ void mma_fp16(float* d, const uint32_t* a,
                                         const uint32_t* b, const float* c) {
    asm volatile(
        "mma.sync.aligned.m16n8k16.row.col.f32.f16.f16.f32 "
        "{%0,%1,%2,%3}, {%4,%5,%6,%7}, {%8,%9}, {%10,%11,%12,%13};\n"
        : "=f"(d[0]), "=f"(d[1]), "=f"(d[2]), "=f"(d[3])
        : "r"(a[0]), "r"(a[1]), "r"(a[2]), "r"(a[3]),
          "r"(b[0]), "r"(b[1]),
          "f"(c[0]), "f"(c[1]), "f"(c[2]), "f"(c[3]));
}
__device__ __forceinline__ void ldsm_x4(uint32_t* r, uint32_t saddr) {
    asm volatile(
        "ldmatrix.sync.aligned.m8n8.x4.shared.b16 {%0,%1,%2,%3}, [%4];\n"
        : "=r"(r[0]), "=r"(r[1]), "=r"(r[2]), "=r"(r[3]) : "r"(saddr));
}
__device__ __forceinline__ void ldsm_x4_t(uint32_t* r, uint32_t saddr) {
    asm volatile(
        "ldmatrix.sync.aligned.m8n8.x4.trans.shared.b16 {%0,%1,%2,%3}, [%4];\n"
        : "=r"(r[0]), "=r"(r[1]), "=r"(r[2]), "=r"(r[3]) : "r"(saddr));
}
__device__ __forceinline__ void cp16(uint32_t saddr, const void* g) {
    asm volatile("cp.async.cg.shared.global [%0], [%1], 16;\n"
                 :: "r"(saddr), "l"(g));
}
__device__ __forceinline__ void cp_commit() {
    asm volatile("cp.async.commit_group;\n" ::: "memory");
}
__device__ __forceinline__ void cp_wait0() {
    asm volatile("cp.async.wait_group 0;\n" ::: "memory");
}
__device__ __forceinline__ void cp_wait2() {
    asm volatile("cp.async.wait_group 2;\n" ::: "memory");
}
__device__ __forceinline__ uint32_t s2u(const void* p) {
    return (uint32_t)__cvta_generic_to_shared(p);
}

// ---------------------------------------------------------------------------
// prep kernels
// ---------------------------------------------------------------------------
__global__ __launch_bounds__(256) void round_fp16_kernel(
    const float4* __restrict__ src, uint2* __restrict__ dst)
{
    const int i = blockIdx.x * 256 + threadIdx.x;
    float4 v = src[i];
    dst[i] = make_uint2(packh2(v.x, v.y), packh2(v.z, v.w));
}

// pack weights [K][N] fp32 -> [K/2][N] half2 k-pair words
__global__ __launch_bounds__(256) void pack_w_fp16_kernel(
    const float* __restrict__ src, uint32_t* __restrict__ dst, int N)
{
    const int idx = blockIdx.x * 256 + threadIdx.x;
    const int kw = idx / N;
    const int n  = idx - kw * N;
    dst[idx] = packh2(src[(size_t)(2 * kw) * N + n],
                      src[(size_t)(2 * kw + 1) * N + n]);
}

// ---------------------------------------------------------------------------
// fp16 GEMM mainloop macro pieces (shared by both GEMM kernels)
// 4-stage cp.async pipeline: 3 tiles in flight, wait_group 2.
// ---------------------------------------------------------------------------
#define GAS 20
#define GBS 136
#define GEMM_BM 64
#define GEMM_A_W (GEMM_BM * GAS)
#define GEMM_B_W (16 * GBS)
#define GEMM_STAGE_W (GEMM_A_W + GEMM_B_W)
#define GEMM_NSTAGE 4
#define GEMM_SMEM_BYTES (GEMM_NSTAGE * GEMM_STAGE_W * 4)   // 55296

#define GEMM_PROLOGUE()                                                        \
    extern __shared__ uint32_t sh[];                                           \
    const int tid  = threadIdx.x;                                              \
    const int lane = tid & 31;                                                 \
    const int wid  = tid >> 5;                                                 \
    const int wm   = wid >> 2;                                                 \
    const int wn   = wid & 3;                                                  \
    const int lr   = lane >> 2;                                                \
    const int lc   = lane & 3;                                                 \
    const int brow = blockIdx.y * GEMM_BM;                                     \
    const int bcol = blockIdx.x * 128;                                         \
    const int K2   = K >> 1;                                                   \
    const int ar = tid >> 2;                                                   \
    const int aw = (tid & 3) * 4;                                              \
    const int br = tid >> 4;                                                   \
    const int bw = (tid & 15) * 4;                                             \
    const uint32_t s_base = s2u(sh);                                           \
    float acc[2][4][4];                                                        \
    _Pragma("unroll")                                                          \
    for (int mf = 0; mf < 2; mf++)                                             \
        _Pragma("unroll")                                                      \
        for (int nf = 0; nf < 4; nf++)                                         \
            _Pragma("unroll")                                                  \
            for (int i = 0; i < 4; i++) acc[mf][nf][i] = 0.f;                  \
    const int ntk = K >> 5;

#define GEMM_ISSUE(KT, BUF)                                                    \
    do {                                                                       \
        const int k0w = (KT) * 16;                                             \
        const uint32_t abuf = s_base + (BUF) * GEMM_STAGE_W * 4;               \
        const uint32_t bbuf = abuf + GEMM_A_W * 4;                             \
        cp16(abuf + (ar * GAS + aw) * 4,                                       \
             A + (size_t)(brow + ar) * K2 + k0w + aw);                         \
        _Pragma("unroll")                                                      \
        for (int i = 0; i < 2; i++) {                                          \
            cp16(bbuf + (br * GBS + bw + 64 * i) * 4,                          \
                 Bp + (size_t)(k0w + br) * N + bcol + bw + 64 * i);            \
        }                                                                      \
        cp_commit();                                                           \
    } while (0)

#define GEMM_MAINLOOP()                                                        \
    GEMM_ISSUE(0, 0);                                                          \
    GEMM_ISSUE(1, 1);                                                          \
    GEMM_ISSUE(2, 2);                                                          \
    for (int kt = 0; kt < ntk; kt++) {                                         \
        cp_wait2();                                                            \
        __syncthreads();                                                       \
        if (kt + 3 < ntk) GEMM_ISSUE(kt + 3, (kt + 3) & 3);                    \
        else cp_commit();                                                      \
        const uint32_t* Ab = sh + (kt & 3) * GEMM_STAGE_W;                     \
        const uint32_t* Bb = Ab + GEMM_A_W;                                    \
        _Pragma("unroll")                                                      \
        for (int ks = 0; ks < 2; ks++) {                                       \
            const int kk = ks * 8;                                             \
            uint32_t af[2][4], bf[4][2];                                       \
            _Pragma("unroll")                                                  \
            for (int mf = 0; mf < 2; mf++) {                                   \
                const int r = wm * 32 + mf * 16 + lr;                          \
                af[mf][0] = Ab[r * GAS + kk + lc];                             \
                af[mf][1] = Ab[(r + 8) * GAS + kk + lc];                       \
                af[mf][2] = Ab[r * GAS + kk + lc + 4];                         \
                af[mf][3] = Ab[(r + 8) * GAS + kk + lc + 4];                   \
            }                                                                  \
            _Pragma("unroll")                                                  \
            for (int nf = 0; nf < 4; nf++) {                                   \
                const int c = wn * 32 + nf * 8 + lr;                           \
                bf[nf][0] = Bb[(kk + lc) * GBS + c];                           \
                bf[nf][1] = Bb[(kk + lc + 4) * GBS + c];                       \
            }                                                                  \
            _Pragma("unroll")                                                  \
            for (int mf = 0; mf < 2; mf++)                                     \
                _Pragma("unroll")                                              \
                for (int nf = 0; nf < 4; nf++)                                 \
                    mma_fp16(acc[mf][nf], af[mf], bf[nf], acc[mf][nf]);        \
        }                                                                      \
    }

// ---------------------------------------------------------------------------
// O-proj GEMM: fp32 C output
// ---------------------------------------------------------------------------
__global__ __launch_bounds__(256, 3) void gemm_fp16(
    const uint32_t* __restrict__ A, const uint32_t* __restrict__ Bp,
    float* __restrict__ C, int M, int N, int K)
{
    GEMM_PROLOGUE();
    GEMM_MAINLOOP();

#pragma unroll
    for (int mf = 0; mf < 2; mf++)
#pragma unroll
        for (int nf = 0; nf < 4; nf++) {
            const int r = brow + wm * 32 + mf * 16 + lr;
            const int c = bcol + wn * 32 + nf * 8 + 2 * lc;
            *(float2*)(C + (size_t)r * N + c) =
                make_float2(acc[mf][nf][0], acc[mf][nf][1]);
            *(float2*)(C + (size_t)(r + 8) * N + c) =
                make_float2(acc[mf][nf][2], acc[mf][nf][3]);
        }
}

// ---------------------------------------------------------------------------
// QKV GEMM with fused mRoPE epilogue.
// blocks 0..15 Q (rope), 16..19 K (rope), 20..23 V (plain fp16 dim-pairs).
// ---------------------------------------------------------------------------
__global__ __launch_bounds__(256, 3) void gemm_fp16_qkv(
    const uint32_t* __restrict__ A, const uint32_t* __restrict__ Bp,
    const int* __restrict__ positions, int M, int N, int K)
{
    GEMM_PROLOGUE();
    GEMM_MAINLOOP();

    const int hb = blockIdx.x;   // head block 0..23

    if (hb >= 20) {              // V: plain fp16 dim-pair store
        uint32_t* vout = g_v_h + (size_t)(hb - 20) * T_SEQ * 64;
#pragma unroll
        for (int mf = 0; mf < 2; mf++)
#pragma unroll
            for (int nf = 0; nf < 4; nf++) {
                const int r = brow + wm * 32 + mf * 16 + lr;
                const int j = wn * 16 + nf * 4 + lc;
                vout[(size_t)r * 64 + j] = packh2(acc[mf][nf][0], acc[mf][nf][1]);
                vout[(size_t)(r + 8) * 64 + j] = packh2(acc[mf][nf][2], acc[mf][nf][3]);
            }
        return;
    }

    const bool isq = (hb < N_HEADS);
#pragma unroll
    for (int nf = 0; nf < 4; nf++) {
        const int j = wn * 16 + nf * 4 + lc;     // dim-pair index 0..63
        const int prow = (j >= 44) ? 0 : ((j & 1) ? 2 : 1);
        const float inv = expf(-((float)j * (1.0f / 64.0f)) * 13.122363377404328f);
#pragma unroll
        for (int mf = 0; mf < 2; mf++)
#pragma unroll
            for (int half = 0; half < 2; half++) {
                const int r = brow + wm * 32 + mf * 16 + lr + half * 8;
                const float pos = (float)positions[prow * T_SEQ + r];
                float sn, cs;
                sincosf(pos * inv, &sn, &cs);
                const float x1 = acc[mf][nf][2 * half];
                const float x2 = acc[mf][nf][2 * half + 1];
                const uint32_t w = packh2(x1 * cs - x2 * sn, x2 * cs + x1 * sn);
                if (isq)
                    g_q_h[(size_t)r * (N_HEADS * 64) + hb * 64 + j] = w;
                else
                    g_k_h[(size_t)(hb - N_HEADS) * T_SEQ * 64 + (size_t)r * 64 + j] = w;
            }
    }
}

// ---------------------------------------------------------------------------
// Causal flash attention, full fp16 MMA with ldmatrix fragment loads
// (R15 version, best known).
// ---------------------------------------------------------------------------
#define AKS2 68
#define ATTN_SMEM_WORDS (2 * (64 * AKS2 + 64 * AKS2))
#define ATTN_SMEM_BYTES (ATTN_SMEM_WORDS * 4)

__global__ __launch_bounds__(256) void attn_tc_kernel()
{
    extern __shared__ uint32_t sm[];
    uint32_t* Kr = sm;                  // [2][64][68]
    uint32_t* Vr = Kr + 2 * 64 * AKS2;  // [2][64][68]

    const int tid  = threadIdx.x;
    const int lane = tid & 31;
    const int wid  = tid >> 5;          // 0..7 : query rows 16*wid
    const int lr   = lane >> 2;
    const int lc   = lane & 3;
    const int lmr  = lane & 7;          // ldmatrix row within matrix
    const int lmi  = lane >> 3;         // ldmatrix matrix index
    const int h    = blockIdx.y;
    const int qb   = gridDim.x - 1 - blockIdx.x;   // big tiles first
    const int kvh  = h >> 2;

    const int row0 = qb * 128 + wid * 16 + lr;

    const uint32_t kr_base = s2u(Kr);
    const uint32_t vr_base = s2u(Vr);

    const uint32_t* Kg = g_k_h + (size_t)kvh * T_SEQ * 64;
    const uint32_t* Vg = g_v_h + (size_t)kvh * T_SEQ * 64;

#define ATTN_ISSUE(J, BUF)                                                     \
    do {                                                                       \
        const uint32_t kb = kr_base + (BUF) * 64 * AKS2 * 4;                   \
        const uint32_t vb = vr_base + (BUF) * 64 * AKS2 * 4;                   \
        _Pragma("unroll")                                                      \
        for (int i = 0; i < 4; i++) {                                          \
            const int id = tid + 256 * i;                                      \
            const int r = id >> 4;                                             \
            const int w = (id & 15) * 4;                                       \
            cp16(kb + (r * AKS2 + w) * 4,                                      \
                 Kg + (size_t)((J) * 64 + r) * 64 + w);                        \
            cp16(vb + (r * AKS2 + w) * 4,                                      \
                 Vg + (size_t)((J) * 64 + r) * 64 + w);                        \
        }                                                                      \
        cp_commit();                                                           \
    } while (0)

    ATTN_ISSUE(0, 0);

    // ---- Q fragments from gmem fp16 (8 k-groups of 16 dims) ----
    uint32_t qf[8][4];
    {
        const uint32_t* q0 = g_q_h + (size_t)row0 * (N_HEADS * 64) + h * 64;
        const uint32_t* q8 = q0 + 8 * (size_t)(N_HEADS * 64);
#pragma unroll
        for (int ks = 0; ks < 8; ks++) {
            qf[ks][0] = q0[8 * ks + lc];
            qf[ks][1] = q8[8 * ks + lc];
            qf[ks][2] = q0[8 * ks + lc + 4];
            qf[ks][3] = q8[8 * ks + lc + 4];
        }
    }

    float m0 = -1e30f, m1 = -1e30f, l0 = 0.f, l1 = 0.f;
    float o[16][4];
#pragma unroll
    for (int nf = 0; nf < 16; nf++)
#pragma unroll
        for (int i = 0; i < 4; i++) o[nf][i] = 0.f;

    const float scale = 0.08838834764831844f;   // 128^-0.5
    const int jmax = 2 * qb + 1;
    const int wrow_lo = qb * 128 + wid * 16;

    // per-lane ldmatrix address pieces
    const int k_row_off = ((lmi >> 1) << 3) + lmr;   // + np*16 keys
    const int k_word_off = (lmi & 1) << 2;           // 0 or 4
    const int v_row_off = ((lmi & 1) << 3) + lmr;    // + ks*16 keys
    const int v_word_off = (lmi >> 1) << 2;          // + np2*8 words

    for (int j = 0; j <= jmax; j++) {
        cp_wait0();
        __syncthreads();
        if (j < jmax) ATTN_ISSUE(j + 1, (j + 1) & 1);

        const bool active = (64 * j <= wrow_lo + 15);
        if (active) {
            const uint32_t kbA = kr_base + (j & 1) * 64 * AKS2 * 4;
            const uint32_t vbA = vr_base + (j & 1) * 64 * AKS2 * 4;

            // ---- scores = Q @ K^T : warp tile 16 x 64 ----
            float sc[8][4];
#pragma unroll
            for (int nf = 0; nf < 8; nf++)
#pragma unroll
                for (int i = 0; i < 4; i++) sc[nf][i] = 0.f;

            uint32_t kaddr[4];
#pragma unroll
            for (int np = 0; np < 4; np++)
                kaddr[np] = kbA + ((np * 16 + k_row_off) * AKS2 + k_word_off) * 4;

#pragma unroll
            for (int ks = 0; ks < 8; ks++) {
#pragma unroll
                for (int np = 0; np < 4; np++) {
                    uint32_t bm[4];
                    ldsm_x4(bm, kaddr[np] + ks * 32);
                    mma_fp16(sc[2 * np],     qf[ks], &bm[0], sc[2 * np]);
                    mma_fp16(sc[2 * np + 1], qf[ks], &bm[2], sc[2 * np + 1]);
                }
            }

            // ---- scale + causal mask ----
            const bool needmask = (64 * j + 63 > wrow_lo);
#pragma unroll
            for (int nf = 0; nf < 8; nf++)
#pragma unroll
                for (int ci = 0; ci < 4; ci++) {
                    float s = sc[nf][ci] * scale;
                    if (needmask) {
                        const int col = 64 * j + nf * 8 + 2 * lc + (ci & 1);
                        const int row = row0 + ((ci >> 1) * 8);
                        if (col > row) s = -1e30f;
                    }
                    sc[nf][ci] = s;
                }

            // ---- warp-local row max ----
            float mx0 = sc[0][0], mx1 = sc[0][2];
#pragma unroll
            for (int nf = 0; nf < 8; nf++) {
                mx0 = fmaxf(mx0, fmaxf(sc[nf][0], sc[nf][1]));
                mx1 = fmaxf(mx1, fmaxf(sc[nf][2], sc[nf][3]));
            }
            mx0 = fmaxf(mx0, __shfl_xor_sync(0xffffffffu, mx0, 1));
            mx0 = fmaxf(mx0, __shfl_xor_sync(0xffffffffu, mx0, 2));
            mx1 = fmaxf(mx1, __shfl_xor_sync(0xffffffffu, mx1, 1));
            mx1 = fmaxf(mx1, __shfl_xor_sync(0xffffffffu, mx1, 2));

            const float mn0 = fmaxf(m0, mx0);
            const float mn1 = fmaxf(m1, mx1);
            const float a0 = __expf(m0 - mn0);
            const float a1 = __expf(m1 - mn1);
            m0 = mn0; m1 = mn1;

            // ---- p = exp(s - m); row sums ----
            float ls0 = 0.f, ls1 = 0.f;
#pragma unroll
            for (int nf = 0; nf < 8; nf++) {
                sc[nf][0] = __expf(sc[nf][0] - mn0);
                sc[nf][1] = __expf(sc[nf][1] - mn0);
                sc[nf][2] = __expf(sc[nf][2] - mn1);
                sc[nf][3] = __expf(sc[nf][3] - mn1);
                ls0 += sc[nf][0] + sc[nf][1];
                ls1 += sc[nf][2] + sc[nf][3];
            }
            ls0 += __shfl_xor_sync(0xffffffffu, ls0, 1);
            ls0 += __shfl_xor_sync(0xffffffffu, ls0, 2);
            ls1 += __shfl_xor_sync(0xffffffffu, ls1, 1);
            ls1 += __shfl_xor_sync(0xffffffffu, ls1, 2);
            l0 = l0 * a0 + ls0;
            l1 = l1 * a1 + ls1;

            // ---- rescale output accumulators ----
#pragma unroll
            for (int nf = 0; nf < 16; nf++) {
                o[nf][0] *= a0; o[nf][1] *= a0;
                o[nf][2] *= a1; o[nf][3] *= a1;
            }

            // ---- PV: pack P (C-frag == A-frag), V via ldsm.trans ----
#pragma unroll
            for (int ks = 0; ks < 4; ks++) {
                uint32_t pf[4];
                pf[0] = packh2(sc[2 * ks][0],     sc[2 * ks][1]);
                pf[1] = packh2(sc[2 * ks][2],     sc[2 * ks][3]);
                pf[2] = packh2(sc[2 * ks + 1][0], sc[2 * ks + 1][1]);
                pf[3] = packh2(sc[2 * ks + 1][2], sc[2 * ks + 1][3]);

                const uint32_t vrow = vbA + ((ks * 16 + v_row_off) * AKS2 + v_word_off) * 4;
#pragma unroll
                for (int np2 = 0; np2 < 8; np2++) {
                    uint32_t bm[4];
                    ldsm_x4_t(bm, vrow + np2 * 32);
                    mma_fp16(o[2 * np2],     pf, &bm[0], o[2 * np2]);
                    mma_fp16(o[2 * np2 + 1], pf, &bm[2], o[2 * np2 + 1]);
                }
            }
        }
    }
#undef ATTN_ISSUE

    // ---- epilogue: normalize, store fp16 (A-side of O-proj) ----
    const float i0 = 1.0f / l0;
    const float i1 = 1.0f / l1;
#pragma unroll
    for (int nf = 0; nf < 16; nf++) {
        const int cw = (h * HEAD_DIM + nf * 8 + 2 * lc) >> 1;
        g_attn_h[(size_t)row0 * (O_DIM / 2) + cw] =
            packh2(o[nf][0] * i0, o[nf][1] * i0);
        g_attn_h[(size_t)(row0 + 8) * (O_DIM / 2) + cw] =
            packh2(o[nf][2] * i1, o[nf][3] * i1);
    }
}

// ---------------------------------------------------------------------------
// Launch
// ---------------------------------------------------------------------------
extern "C" void kernel_launch(void* const* d_in, const int* in_sizes, int n_in,
                              void* d_out, int out_size)
{
    const int*   positions = (const int*)d_in[0];
    const float* hidden    = (const float*)d_in[1];
    const float* w_qkv     = (const float*)d_in[2];
    const float* w_o       = (const float*)d_in[3];
    float*       out       = (float*)d_out;

    uint32_t *attn_ptr, *hid_ptr, *wqkv_ptr, *wo_ptr;
    cudaGetSymbolAddress((void**)&attn_ptr, g_attn_h);
    cudaGetSymbolAddress((void**)&hid_ptr,  g_hid_h);
    cudaGetSymbolAddress((void**)&wqkv_ptr, g_wqkv_h);
    cudaGetSymbolAddress((void**)&wo_ptr,   g_wo_h);

    static int cfg = 0;
    if (!cfg) {
        cudaFuncSetAttribute(gemm_fp16,
                             cudaFuncAttributeMaxDynamicSharedMemorySize,
                             GEMM_SMEM_BYTES);
        cudaFuncSetAttribute(gemm_fp16_qkv,
                             cudaFuncAttributeMaxDynamicSharedMemorySize,
                             GEMM_SMEM_BYTES);
        cudaFuncSetAttribute(attn_tc_kernel,
                             cudaFuncAttributeMaxDynamicSharedMemorySize,
                             ATTN_SMEM_BYTES);
        cfg = 1;
    }

    // 0) prep: fp16 convert activations; pack weights as k-pair half2
    round_fp16_kernel<<<(T_SEQ * HIDDEN) / 1024, 256>>>(
        (const float4*)hidden, (uint2*)hid_ptr);
    pack_w_fp16_kernel<<<((HIDDEN / 2) * QKV_N) / 256, 256>>>(
        w_qkv, wqkv_ptr, QKV_N);
    pack_w_fp16_kernel<<<((O_DIM / 2) * HIDDEN) / 256, 256>>>(
        w_o, wo_ptr, HIDDEN);

    // 1) QKV projection with fused mRoPE -> fp16 Q/K/V buffers
    gemm_fp16_qkv<<<dim3(QKV_N / 128, T_SEQ / GEMM_BM), 256, GEMM_SMEM_BYTES>>>(
        hid_ptr, wqkv_ptr, positions, T_SEQ, QKV_N, HIDDEN);

    // 2) Causal flash attention (fp16 MMA + ldmatrix) -> fp16 output
    attn_tc_kernel<<<dim3(T_SEQ / 128, N_HEADS), 256, ATTN_SMEM_BYTES>>>();

    // 3) Output projection (fp16 MMA) -> fp32 out
    gemm_fp16<<<dim3(O_DIM / 128, T_SEQ / GEMM_BM), 256, GEMM_SMEM_BYTES>>>(
        attn_ptr, wo_ptr, out, T_SEQ, O_DIM, HIDDEN);
}

// round 17
// speedup vs baseline: 1.5236x; 1.5236x over previous
#include <cuda_runtime.h>
#include <cuda_fp16.h>
#include <math.h>
#include <stdint.h>
#include <string.h>

// ---------------------------------------------------------------------------
// Problem constants
// ---------------------------------------------------------------------------
#define T_SEQ   2048
#define HIDDEN  2048
#define N_HEADS 16
#define N_KV    4
#define HEAD_DIM 128
#define QKV_N   ((N_HEADS + 2 * N_KV) * HEAD_DIM)   // 3072
#define O_DIM   (N_HEADS * HEAD_DIM)                 // 2048

__device__ uint32_t g_attn_h[T_SEQ * O_DIM / 2];        // fp16 attn out
__device__ uint32_t g_hid_h[T_SEQ * HIDDEN / 2];        // fp16 hidden
__device__ uint32_t g_wqkv_h[(HIDDEN / 2) * QKV_N];     // fp16 w_qkv k-pairs
__device__ uint32_t g_wo_h[(O_DIM / 2) * HIDDEN];       // fp16 w_o   k-pairs
__device__ uint32_t g_q_h[T_SEQ * N_HEADS * 64];        // fp16 Q dim-pairs
__device__ uint32_t g_k_h[N_KV * T_SEQ * 64];           // fp16 K dim-pairs
__device__ uint32_t g_v_h[N_KV * T_SEQ * 64];           // fp16 V dim-pairs

// ---------------------------------------------------------------------------
// helpers
// ---------------------------------------------------------------------------
__device__ __forceinline__ uint32_t packh2(float a, float b) {
    __half2 h = __floats2half2_rn(a, b);
    uint32_t u; memcpy(&u, &h, 4); return u;
}
__device__ __forceinline__ void mma_fp16(float* d, const uint32_t* a,
                                         const uint32_t* b, const float* c) {
    asm volatile(
        "mma.sync.aligned.m16n8k16.row.col.f32.f16.f16.f32 "
        "{%0,%1,%2,%3}, {%4,%5,%6,%7}, {%8,%9}, {%10,%11,%12,%13};\n"
        : "=f"(d[0]), "=f"(d[1]), "=f"(d[2]), "=f"(d[3])
        : "r"(a[0]), "r"(a[1]), "r"(a[2]), "r"(a[3]),
          "r"(b[0]), "r"(b[1]),
          "f"(c[0]), "f"(c[1]), "f"(c[2]), "f"(c[3]));
}
__device__ __forceinline__ void ldsm_x4(uint32_t* r, uint32_t saddr) {
    asm volatile(
        "ldmatrix.sync.aligned.m8n8.x4.shared.b16 {%0,%1,%2,%3}, [%4];\n"
        : "=r"(r[0]), "=r"(r[1]), "=r"(r[2]), "=r"(r[3]) : "r"(saddr));
}
__device__ __forceinline__ void ldsm_x4_t(uint32_t* r, uint32_t saddr) {
    asm volatile(
        "ldmatrix.sync.aligned.m8n8.x4.trans.shared.b16 {%0,%1,%2,%3}, [%4];\n"
        : "=r"(r[0]), "=r"(r[1]), "=r"(r[2]), "=r"(r[3]) : "r"(saddr));
}
__device__ __forceinline__ void cp16(uint32_t saddr, const void* g) {
    asm volatile("cp.async.cg.shared.global [%0], [%1], 16;\n"
                 :: "r"(saddr), "l"(g));
}
__device__ __forceinline__ void cp_commit() {
    asm volatile("cp.async.commit_group;\n" ::: "memory");
}
__device__ __forceinline__ void cp_wait0() {
    asm volatile("cp.async.wait_group 0;\n" ::: "memory");
}
__device__ __forceinline__ void cp_wait1() {
    asm volatile("cp.async.wait_group 1;\n" ::: "memory");
}
__device__ __forceinline__ uint32_t s2u(const void* p) {
    return (uint32_t)__cvta_generic_to_shared(p);
}

// ---------------------------------------------------------------------------
// prep kernels
// ---------------------------------------------------------------------------
__global__ __launch_bounds__(256) void round_fp16_kernel(
    const float4* __restrict__ src, uint2* __restrict__ dst)
{
    const int i = blockIdx.x * 256 + threadIdx.x;
    float4 v = src[i];
    dst[i] = make_uint2(packh2(v.x, v.y), packh2(v.z, v.w));
}

// pack weights [K][N] fp32 -> [K/2][N] half2 k-pair words
__global__ __launch_bounds__(256) void pack_w_fp16_kernel(
    const float* __restrict__ src, uint32_t* __restrict__ dst, int N)
{
    const int idx = blockIdx.x * 256 + threadIdx.x;
    const int kw = idx / N;
    const int n  = idx - kw * N;
    dst[idx] = packh2(src[(size_t)(2 * kw) * N + n],
                      src[(size_t)(2 * kw + 1) * N + n]);
}

// ---------------------------------------------------------------------------
// fp16 GEMM mainloop macro pieces (shared by both GEMM kernels)
// 3-stage cp.async pipeline: 2 tiles in flight, wait_group 1.
// ---------------------------------------------------------------------------
#define GAS 20
#define GBS 136
#define GEMM_BM 64
#define GEMM_A_W (GEMM_BM * GAS)
#define GEMM_B_W (16 * GBS)
#define GEMM_STAGE_W (GEMM_A_W + GEMM_B_W)
#define GEMM_NSTAGE 3
#define GEMM_SMEM_BYTES (GEMM_NSTAGE * GEMM_STAGE_W * 4)   // 41472

#define GEMM_PROLOGUE()                                                        \
    extern __shared__ uint32_t sh[];                                           \
    const int tid  = threadIdx.x;                                              \
    const int lane = tid & 31;                                                 \
    const int wid  = tid >> 5;                                                 \
    const int wm   = wid >> 2;                                                 \
    const int wn   = wid & 3;                                                  \
    const int lr   = lane >> 2;                                                \
    const int lc   = lane & 3;                                                 \
    const int brow = blockIdx.y * GEMM_BM;                                     \
    const int bcol = blockIdx.x * 128;                                         \
    const int K2   = K >> 1;                                                   \
    const int ar = tid >> 2;                                                   \
    const int aw = (tid & 3) * 4;                                              \
    const int br = tid >> 4;                                                   \
    const int bw = (tid & 15) * 4;                                             \
    const uint32_t s_base = s2u(sh);                                           \
    float acc[2][4][4];                                                        \
    _Pragma("unroll")                                                          \
    for (int mf = 0; mf < 2; mf++)                                             \
        _Pragma("unroll")                                                      \
        for (int nf = 0; nf < 4; nf++)                                         \
            _Pragma("unroll")                                                  \
            for (int i = 0; i < 4; i++) acc[mf][nf][i] = 0.f;                  \
    const int ntk = K >> 5;

#define GEMM_ISSUE(KT, BUF)                                                    \
    do {                                                                       \
        const int k0w = (KT) * 16;                                             \
        const uint32_t abuf = s_base + (BUF) * GEMM_STAGE_W * 4;               \
        const uint32_t bbuf = abuf + GEMM_A_W * 4;                             \
        cp16(abuf + (ar * GAS + aw) * 4,                                       \
             A + (size_t)(brow + ar) * K2 + k0w + aw);                         \
        _Pragma("unroll")                                                      \
        for (int i = 0; i < 2; i++) {                                          \
            cp16(bbuf + (br * GBS + bw + 64 * i) * 4,                          \
                 Bp + (size_t)(k0w + br) * N + bcol + bw + 64 * i);            \
        }                                                                      \
        cp_commit();                                                           \
    } while (0)

#define GEMM_MAINLOOP()                                                        \
    GEMM_ISSUE(0, 0);                                                          \
    GEMM_ISSUE(1, 1);                                                          \
    for (int kt = 0; kt < ntk; kt++) {                                         \
        cp_wait1();                                                            \
        __syncthreads();                                                       \
        if (kt + 2 < ntk) {                                                    \
            const int b2 = (kt + 2) % 3;                                       \
            GEMM_ISSUE(kt + 2, b2);                                            \
        } else cp_commit();                                                    \
        const uint32_t* Ab = sh + (kt % 3) * GEMM_STAGE_W;                     \
        const uint32_t* Bb = Ab + GEMM_A_W;                                    \
        _Pragma("unroll")                                                      \
        for (int ks = 0; ks < 2; ks++) {                                       \
            const int kk = ks * 8;                                             \
            uint32_t af[2][4], bf[4][2];                                       \
            _Pragma("unroll")                                                  \
            for (int mf = 0; mf < 2; mf++) {                                   \
                const int r = wm * 32 + mf * 16 + lr;                          \
                af[mf][0] = Ab[r * GAS + kk + lc];                             \
                af[mf][1] = Ab[(r + 8) * GAS + kk + lc];                       \
                af[mf][2] = Ab[r * GAS + kk + lc + 4];                         \
                af[mf][3] = Ab[(r + 8) * GAS + kk + lc + 4];                   \
            }                                                                  \
            _Pragma("unroll")                                                  \
            for (int nf = 0; nf < 4; nf++) {                                   \
                const int c = wn * 32 + nf * 8 + lr;                           \
                bf[nf][0] = Bb[(kk + lc) * GBS + c];                           \
                bf[nf][1] = Bb[(kk + lc + 4) * GBS + c];                       \
            }                                                                  \
            _Pragma("unroll")                                                  \
            for (int mf = 0; mf < 2; mf++)                                     \
                _Pragma("unroll")                                              \
                for (int nf = 0; nf < 4; nf++)                                 \
                    mma_fp16(acc[mf][nf], af[mf], bf[nf], acc[mf][nf]);        \
        }                                                                      \
    }

// ---------------------------------------------------------------------------
// O-proj GEMM: fp32 C output
// ---------------------------------------------------------------------------
__global__ __launch_bounds__(256, 3) void gemm_fp16(
    const uint32_t* __restrict__ A, const uint32_t* __restrict__ Bp,
    float* __restrict__ C, int M, int N, int K)
{
    GEMM_PROLOGUE();
    GEMM_MAINLOOP();

#pragma unroll
    for (int mf = 0; mf < 2; mf++)
#pragma unroll
        for (int nf = 0; nf < 4; nf++) {
            const int r = brow + wm * 32 + mf * 16 + lr;
            const int c = bcol + wn * 32 + nf * 8 + 2 * lc;
            *(float2*)(C + (size_t)r * N + c) =
                make_float2(acc[mf][nf][0], acc[mf][nf][1]);
            *(float2*)(C + (size_t)(r + 8) * N + c) =
                make_float2(acc[mf][nf][2], acc[mf][nf][3]);
        }
}

// ---------------------------------------------------------------------------
// QKV GEMM with fused mRoPE epilogue.
// blocks 0..15 Q (rope), 16..19 K (rope), 20..23 V (plain fp16 dim-pairs).
// ---------------------------------------------------------------------------
__global__ __launch_bounds__(256, 3) void gemm_fp16_qkv(
    const uint32_t* __restrict__ A, const uint32_t* __restrict__ Bp,
    const int* __restrict__ positions, int M, int N, int K)
{
    GEMM_PROLOGUE();
    GEMM_MAINLOOP();

    const int hb = blockIdx.x;   // head block 0..23

    if (hb >= 20) {              // V: plain fp16 dim-pair store
        uint32_t* vout = g_v_h + (size_t)(hb - 20) * T_SEQ * 64;
#pragma unroll
        for (int mf = 0; mf < 2; mf++)
#pragma unroll
            for (int nf = 0; nf < 4; nf++) {
                const int r = brow + wm * 32 + mf * 16 + lr;
                const int j = wn * 16 + nf * 4 + lc;
                vout[(size_t)r * 64 + j] = packh2(acc[mf][nf][0], acc[mf][nf][1]);
                vout[(size_t)(r + 8) * 64 + j] = packh2(acc[mf][nf][2], acc[mf][nf][3]);
            }
        return;
    }

    const bool isq = (hb < N_HEADS);
#pragma unroll
    for (int nf = 0; nf < 4; nf++) {
        const int j = wn * 16 + nf * 4 + lc;     // dim-pair index 0..63
        const int prow = (j >= 44) ? 0 : ((j & 1) ? 2 : 1);
        const float inv = expf(-((float)j * (1.0f / 64.0f)) * 13.122363377404328f);
#pragma unroll
        for (int mf = 0; mf < 2; mf++)
#pragma unroll
            for (int half = 0; half < 2; half++) {
                const int r = brow + wm * 32 + mf * 16 + lr + half * 8;
                const float pos = (float)positions[prow * T_SEQ + r];
                float sn, cs;
                sincosf(pos * inv, &sn, &cs);
                const float x1 = acc[mf][nf][2 * half];
                const float x2 = acc[mf][nf][2 * half + 1];
                const uint32_t w = packh2(x1 * cs - x2 * sn, x2 * cs + x1 * sn);
                if (isq)
                    g_q_h[(size_t)r * (N_HEADS * 64) + hb * 64 + j] = w;
                else
                    g_k_h[(size_t)(hb - N_HEADS) * T_SEQ * 64 + (size_t)r * 64 + j] = w;
            }
    }
}

// ---------------------------------------------------------------------------
// Causal flash attention, full fp16 MMA with ldmatrix fragment loads
// (R15 version, best known — unchanged).
// ---------------------------------------------------------------------------
#define AKS2 68
#define ATTN_SMEM_WORDS (2 * (64 * AKS2 + 64 * AKS2))
#define ATTN_SMEM_BYTES (ATTN_SMEM_WORDS * 4)

__global__ __launch_bounds__(256) void attn_tc_kernel()
{
    extern __shared__ uint32_t sm[];
    uint32_t* Kr = sm;                  // [2][64][68]
    uint32_t* Vr = Kr + 2 * 64 * AKS2;  // [2][64][68]

    const int tid  = threadIdx.x;
    const int lane = tid & 31;
    const int wid  = tid >> 5;          // 0..7 : query rows 16*wid
    const int lr   = lane >> 2;
    const int lc   = lane & 3;
    const int lmr  = lane & 7;          // ldmatrix row within matrix
    const int lmi  = lane >> 3;         // ldmatrix matrix index
    const int h    = blockIdx.y;
    const int qb   = gridDim.x - 1 - blockIdx.x;   // big tiles first
    const int kvh  = h >> 2;

    const int row0 = qb * 128 + wid * 16 + lr;

    const uint32_t kr_base = s2u(Kr);
    const uint32_t vr_base = s2u(Vr);

    const uint32_t* Kg = g_k_h + (size_t)kvh * T_SEQ * 64;
    const uint32_t* Vg = g_v_h + (size_t)kvh * T_SEQ * 64;

#define ATTN_ISSUE(J, BUF)                                                     \
    do {                                                                       \
        const uint32_t kb = kr_base + (BUF) * 64 * AKS2 * 4;                   \
        const uint32_t vb = vr_base + (BUF) * 64 * AKS2 * 4;                   \
        _Pragma("unroll")                                                      \
        for (int i = 0; i < 4; i++) {                                          \
            const int id = tid + 256 * i;                                      \
            const int r = id >> 4;                                             \
            const int w = (id & 15) * 4;                                       \
            cp16(kb + (r * AKS2 + w) * 4,                                      \
                 Kg + (size_t)((J) * 64 + r) * 64 + w);                        \
            cp16(vb + (r * AKS2 + w) * 4,                                      \
                 Vg + (size_t)((J) * 64 + r) * 64 + w);                        \
        }                                                                      \
        cp_commit();                                                           \
    } while (0)

    ATTN_ISSUE(0, 0);

    // ---- Q fragments from gmem fp16 (8 k-groups of 16 dims) ----
    uint32_t qf[8][4];
    {
        const uint32_t* q0 = g_q_h + (size_t)row0 * (N_HEADS * 64) + h * 64;
        const uint32_t* q8 = q0 + 8 * (size_t)(N_HEADS * 64);
#pragma unroll
        for (int ks = 0; ks < 8; ks++) {
            qf[ks][0] = q0[8 * ks + lc];
            qf[ks][1] = q8[8 * ks + lc];
            qf[ks][2] = q0[8 * ks + lc + 4];
            qf[ks][3] = q8[8 * ks + lc + 4];
        }
    }

    float m0 = -1e30f, m1 = -1e30f, l0 = 0.f, l1 = 0.f;
    float o[16][4];
#pragma unroll
    for (int nf = 0; nf < 16; nf++)
#pragma unroll
        for (int i = 0; i < 4; i++) o[nf][i] = 0.f;

    const float scale = 0.08838834764831844f;   // 128^-0.5
    const int jmax = 2 * qb + 1;
    const int wrow_lo = qb * 128 + wid * 16;

    // per-lane ldmatrix address pieces
    const int k_row_off = ((lmi >> 1) << 3) + lmr;   // + np*16 keys
    const int k_word_off = (lmi & 1) << 2;           // 0 or 4
    const int v_row_off = ((lmi & 1) << 3) + lmr;    // + ks*16 keys
    const int v_word_off = (lmi >> 1) << 2;          // + np2*8 words

    for (int j = 0; j <= jmax; j++) {
        cp_wait0();
        __syncthreads();
        if (j < jmax) ATTN_ISSUE(j + 1, (j + 1) & 1);

        const bool active = (64 * j <= wrow_lo + 15);
        if (active) {
            const uint32_t kbA = kr_base + (j & 1) * 64 * AKS2 * 4;
            const uint32_t vbA = vr_base + (j & 1) * 64 * AKS2 * 4;

            // ---- scores = Q @ K^T : warp tile 16 x 64 ----
            float sc[8][4];
#pragma unroll
            for (int nf = 0; nf < 8; nf++)
#pragma unroll
                for (int i = 0; i < 4; i++) sc[nf][i] = 0.f;

            uint32_t kaddr[4];
#pragma unroll
            for (int np = 0; np < 4; np++)
                kaddr[np] = kbA + ((np * 16 + k_row_off) * AKS2 + k_word_off) * 4;

#pragma unroll
            for (int ks = 0; ks < 8; ks++) {
#pragma unroll
                for (int np = 0; np < 4; np++) {
                    uint32_t bm[4];
                    ldsm_x4(bm, kaddr[np] + ks * 32);
                    mma_fp16(sc[2 * np],     qf[ks], &bm[0], sc[2 * np]);
                    mma_fp16(sc[2 * np + 1], qf[ks], &bm[2], sc[2 * np + 1]);
                }
            }

            // ---- scale + causal mask ----
            const bool needmask = (64 * j + 63 > wrow_lo);
#pragma unroll
            for (int nf = 0; nf < 8; nf++)
#pragma unroll
                for (int ci = 0; ci < 4; ci++) {
                    float s = sc[nf][ci] * scale;
                    if (needmask) {
                        const int col = 64 * j + nf * 8 + 2 * lc + (ci & 1);
                        const int row = row0 + ((ci >> 1) * 8);
                        if (col > row) s = -1e30f;
                    }
                    sc[nf][ci] = s;
                }

            // ---- warp-local row max ----
            float mx0 = sc[0][0], mx1 = sc[0][2];
#pragma unroll
            for (int nf = 0; nf < 8; nf++) {
                mx0 = fmaxf(mx0, fmaxf(sc[nf][0], sc[nf][1]));
                mx1 = fmaxf(mx1, fmaxf(sc[nf][2], sc[nf][3]));
            }
            mx0 = fmaxf(mx0, __shfl_xor_sync(0xffffffffu, mx0, 1));
            mx0 = fmaxf(mx0, __shfl_xor_sync(0xffffffffu, mx0, 2));
            mx1 = fmaxf(mx1, __shfl_xor_sync(0xffffffffu, mx1, 1));
            mx1 = fmaxf(mx1, __shfl_xor_sync(0xffffffffu, mx1, 2));

            const float mn0 = fmaxf(m0, mx0);
            const float mn1 = fmaxf(m1, mx1);
            const float a0 = __expf(m0 - mn0);
            const float a1 = __expf(m1 - mn1);
            m0 = mn0; m1 = mn1;

            // ---- p = exp(s - m); row sums ----
            float ls0 = 0.f, ls1 = 0.f;
#pragma unroll
            for (int nf = 0; nf < 8; nf++) {
                sc[nf][0] = __expf(sc[nf][0] - mn0);
                sc[nf][1] = __expf(sc[nf][1] - mn0);
                sc[nf][2] = __expf(sc[nf][2] - mn1);
                sc[nf][3] = __expf(sc[nf][3] - mn1);
                ls0 += sc[nf][0] + sc[nf][1];
                ls1 += sc[nf][2] + sc[nf][3];
            }
            ls0 += __shfl_xor_sync(0xffffffffu, ls0, 1);
            ls0 += __shfl_xor_sync(0xffffffffu, ls0, 2);
            ls1 += __shfl_xor_sync(0xffffffffu, ls1, 1);
            ls1 += __shfl_xor_sync(0xffffffffu, ls1, 2);
            l0 = l0 * a0 + ls0;
            l1 = l1 * a1 + ls1;

            // ---- rescale output accumulators ----
#pragma unroll
            for (int nf = 0; nf < 16; nf++) {
                o[nf][0] *= a0; o[nf][1] *= a0;
                o[nf][2] *= a1; o[nf][3] *= a1;
            }

            // ---- PV: pack P (C-frag == A-frag), V via ldsm.trans ----
#pragma unroll
            for (int ks = 0; ks < 4; ks++) {
                uint32_t pf[4];
                pf[0] = packh2(sc[2 * ks][0],     sc[2 * ks][1]);
                pf[1] = packh2(sc[2 * ks][2],     sc[2 * ks][3]);
                pf[2] = packh2(sc[2 * ks + 1][0], sc[2 * ks + 1][1]);
                pf[3] = packh2(sc[2 * ks + 1][2], sc[2 * ks + 1][3]);

                const uint32_t vrow = vbA + ((ks * 16 + v_row_off) * AKS2 + v_word_off) * 4;
#pragma unroll
                for (int np2 = 0; np2 < 8; np2++) {
                    uint32_t bm[4];
                    ldsm_x4_t(bm, vrow + np2 * 32);
                    mma_fp16(o[2 * np2],     pf, &bm[0], o[2 * np2]);
                    mma_fp16(o[2 * np2 + 1], pf, &bm[2], o[2 * np2 + 1]);
                }
            }
        }
    }
#undef ATTN_ISSUE

    // ---- epilogue: normalize, store fp16 (A-side of O-proj) ----
    const float i0 = 1.0f / l0;
    const float i1 = 1.0f / l1;
#pragma unroll
    for (int nf = 0; nf < 16; nf++) {
        const int cw = (h * HEAD_DIM + nf * 8 + 2 * lc) >> 1;
        g_attn_h[(size_t)row0 * (O_DIM / 2) + cw] =
            packh2(o[nf][0] * i0, o[nf][1] * i0);
        g_attn_h[(size_t)(row0 + 8) * (O_DIM / 2) + cw] =
            packh2(o[nf][2] * i1, o[nf][3] * i1);
    }
}

// ---------------------------------------------------------------------------
// Launch
// ---------------------------------------------------------------------------
extern "C" void kernel_launch(void* const* d_in, const int* in_sizes, int n_in,
                              void* d_out, int out_size)
{
    const int*   positions = (const int*)d_in[0];
    const float* hidden    = (const float*)d_in[1];
    const float* w_qkv     = (const float*)d_in[2];
    const float* w_o       = (const float*)d_in[3];
    float*       out       = (float*)d_out;

    uint32_t *attn_ptr, *hid_ptr, *wqkv_ptr, *wo_ptr;
    cudaGetSymbolAddress((void**)&attn_ptr, g_attn_h);
    cudaGetSymbolAddress((void**)&hid_ptr,  g_hid_h);
    cudaGetSymbolAddress((void**)&wqkv_ptr, g_wqkv_h);
    cudaGetSymbolAddress((void**)&wo_ptr,   g_wo_h);

    static int cfg = 0;
    if (!cfg) {
        cudaFuncSetAttribute(gemm_fp16,
                             cudaFuncAttributeMaxDynamicSharedMemorySize,
                             GEMM_SMEM_BYTES);
        cudaFuncSetAttribute(gemm_fp16_qkv,
                             cudaFuncAttributeMaxDynamicSharedMemorySize,
                             GEMM_SMEM_BYTES);
        cudaFuncSetAttribute(attn_tc_kernel,
                             cudaFuncAttributeMaxDynamicSharedMemorySize,
                             ATTN_SMEM_BYTES);
        cfg = 1;
    }

    // 0) prep: fp16 convert activations; pack weights as k-pair half2
    round_fp16_kernel<<<(T_SEQ * HIDDEN) / 1024, 256>>>(
        (const float4*)hidden, (uint2*)hid_ptr);
    pack_w_fp16_kernel<<<((HIDDEN / 2) * QKV_N) / 256, 256>>>(
        w_qkv, wqkv_ptr, QKV_N);
    pack_w_fp16_kernel<<<((O_DIM / 2) * HIDDEN) / 256, 256>>>(
        w_o, wo_ptr, HIDDEN);

    // 1) QKV projection with fused mRoPE -> fp16 Q/K/V buffers
    gemm_fp16_qkv<<<dim3(QKV_N / 128, T_SEQ / GEMM_BM), 256, GEMM_SMEM_BYTES>>>(
        hid_ptr, wqkv_ptr, positions, T_SEQ, QKV_N, HIDDEN);

    // 2) Causal flash attention (fp16 MMA + ldmatrix) -> fp16 output
    attn_tc_kernel<<<dim3(T_SEQ / 128, N_HEADS), 256, ATTN_SMEM_BYTES>>>();

    // 3) Output projection (fp16 MMA) -> fp32 out
    gemm_fp16<<<dim3(O_DIM / 128, T_SEQ / GEMM_BM), 256, GEMM_SMEM_BYTES>>>(
        attn_ptr, wo_ptr, out, T_SEQ, O_DIM, HIDDEN);
}